// round 4
// baseline (speedup 1.0000x reference)
#include <cuda_runtime.h>
#include <cuda_fp16.h>
#include <mma.h>
#include <cstdint>

using namespace nvcuda;

#define N_TOT 131072
#define NF    512
#define DQ    128
#define NBAGS 32
#define BM    128            // rows per GEMM block
#define LDA   520            // padded half ld for A tile
#define LDB   520            // padded half ld for B chunk
#define A_BYTES (BM * LDA * 2)         // 133120
#define B_BYTES (64 * LDB * 2)         // 66560
#define SMEM_DYN (A_BYTES + B_BYTES)   // 199680

// ----------------------------- device scratch ------------------------------
__device__ unsigned long long g_argmax[NBAGS];
__device__ int      g_offs[NBAGS + 1];
__device__ float    g_u[NBAGS * NF];
__device__ float    g_cst[NBAGS];
__device__ float    g_vdot[N_TOT];
__device__ float    g_A[N_TOT];
__device__ unsigned g_bagAmax[NBAGS];
__device__ float    g_num[NBAGS];
__device__ float    g_den[NBAGS];
__device__ __align__(16) __half g_WT[NF * NF];   // WT[n][f] = w_v[f][n]

// ----------------------------- helpers -------------------------------------
__device__ __forceinline__ unsigned encf(float x) {
    unsigned u = __float_as_uint(x);
    return (u & 0x80000000u) ? ~u : (u | 0x80000000u);
}
__device__ __forceinline__ float decf(unsigned e) {
    return (e & 0x80000000u) ? __uint_as_float(e & 0x7fffffffu)
                             : __uint_as_float(~e);
}
__device__ __forceinline__ int findbag(const int* offs, int n) {
    int lo = 0, hi = NBAGS - 1;
    while (lo < hi) {
        int mid = (lo + hi + 1) >> 1;
        if (offs[mid] <= n) lo = mid; else hi = mid - 1;
    }
    return lo;
}

// ----------------------------- K0: init ------------------------------------
__global__ void k0_init(const int* __restrict__ split) {
    int t = threadIdx.x;
    if (t < NBAGS) {
        g_argmax[t]  = 0ull;
        g_bagAmax[t] = encf(-3.0e38f);
        g_num[t] = 0.f;
        g_den[t] = 0.f;
    }
    if (t == 0) {
        int s = 0;
        for (int i = 0; i < NBAGS; i++) { g_offs[i] = s; s += split[i]; }
        g_offs[NBAGS] = s;
    }
}

// ----------------------------- Kw: w_v -> WT fp16 ---------------------------
__global__ void kw_prep(const float* __restrict__ w_v) {
    int i = blockIdx.x * 256 + threadIdx.x;       // i = n*512 + f
    int n = i >> 9, f = i & 511;
    g_WT[i] = __float2half(w_v[f * NF + n]);
}

// ------------------- K1: fused c + argmax + vdot GEMM (wmma) ----------------
__global__ void __launch_bounds__(256, 1) k1_gemm(
    const float* __restrict__ feats, const float* __restrict__ w_ins,
    const float* __restrict__ b_ins, const float* __restrict__ b_v,
    const float* __restrict__ fcc_w, float* __restrict__ out_c)
{
    extern __shared__ __align__(16) char smem[];
    __half* sA  = (__half*)smem;                       // [128][LDA]
    __half* sB  = (__half*)(smem + A_BYTES);           // [64][LDB]
    float*  scr = (float*)(smem + A_BYTES);            // reuse: [128][64]
    __shared__ float s_wins[NF], s_bv[NF], s_fcc[NF];
    __shared__ int   s_offs[NBAGS + 1];

    const int tid = threadIdx.x, wid = tid >> 5, lane = tid & 31;
    for (int i = tid; i < NF; i += 256) {
        s_wins[i] = w_ins[i]; s_bv[i] = b_v[i]; s_fcc[i] = fcc_w[i];
    }
    if (tid < NBAGS + 1) s_offs[tid] = g_offs[tid];
    const float b0 = b_ins[0];
    const int rowBase = blockIdx.x * BM;
    __syncthreads();   // FIX: s_wins/s_offs must be fully populated before use

    // stage feats fp32 -> fp16 tile; fuse fp32 c + per-bag argmax
    for (int i = 0; i < 16; i++) {
        int r = wid * 16 + i;
        int grow = rowBase + r;
        const float4* src = (const float4*)(feats + (size_t)grow * NF);
        float cs = 0.f;
        #pragma unroll
        for (int j = 0; j < 4; j++) {
            int c4 = lane + 32 * j;
            float4 v = src[c4];
            int col = c4 << 2;
            cs += v.x * s_wins[col]     + v.y * s_wins[col + 1]
                + v.z * s_wins[col + 2] + v.w * s_wins[col + 3];
            __half2 h0 = __floats2half2_rn(v.x, v.y);
            __half2 h1 = __floats2half2_rn(v.z, v.w);
            *(__half2*)(sA + r * LDA + col)     = h0;
            *(__half2*)(sA + r * LDA + col + 2) = h1;
        }
        #pragma unroll
        for (int o = 16; o; o >>= 1) cs += __shfl_xor_sync(0xffffffffu, cs, o);
        if (lane == 0) {
            float cval = cs + b0;
            out_c[grow] = cval;
            int bag = findbag(s_offs, grow);
            unsigned long long key =
                ((unsigned long long)encf(cval) << 32) | (unsigned)(N_TOT - grow);
            atomicMax(&g_argmax[bag], key);
        }
    }
    __syncthreads();

    float vacc = 0.f;
    const int myrow = tid >> 1, myhalf = tid & 1;

    for (int nc = 0; nc < 8; nc++) {            // 8 chunks of 64 output cols
        const int n0 = nc * 64;
        // load B chunk: sB[n][k], n in [n0, n0+64)
        const uint4* bs = (const uint4*)(g_WT + (size_t)n0 * NF);
        uint4* bd = (uint4*)sB;
        for (int t = tid; t < 4096; t += 256) {
            int n = t >> 6, kk = t & 63;
            bd[n * (LDB / 8) + kk] = bs[n * (NF / 8) + kk];
        }
        __syncthreads();

        wmma::fragment<wmma::accumulator, 16, 16, 16, float> acc[4];
        #pragma unroll
        for (int s = 0; s < 4; s++) wmma::fill_fragment(acc[s], 0.f);

        for (int k0 = 0; k0 < NF; k0 += 16) {
            wmma::fragment<wmma::matrix_a, 16, 16, 16, __half, wmma::row_major> fa;
            wmma::load_matrix_sync(fa, sA + (wid * 16) * LDA + k0, LDA);
            #pragma unroll
            for (int s = 0; s < 4; s++) {
                wmma::fragment<wmma::matrix_b, 16, 16, 16, __half, wmma::col_major> fb;
                wmma::load_matrix_sync(fb, sB + (s * 16) * LDB + k0, LDB);
                wmma::mma_sync(acc[s], fa, fb, acc[s]);
            }
        }
        __syncthreads();                        // B chunk dead -> reuse as scr
        #pragma unroll
        for (int s = 0; s < 4; s++)
            wmma::store_matrix_sync(scr + (wid * 16) * 64 + s * 16, acc[s], 64,
                                    wmma::mem_row_major);
        __syncthreads();
        #pragma unroll
        for (int c = 0; c < 32; c++) {
            int col = myhalf * 32 + c;
            float d = scr[myrow * 64 + col] + s_bv[n0 + col];
            vacc = fmaf(fmaxf(d, 0.f), s_fcc[n0 + col], vacc);
        }
        __syncthreads();
    }
    float other = __shfl_xor_sync(0xffffffffu, vacc, 1);
    if (myhalf == 0) g_vdot[rowBase + myrow] = vacc + other;
}

// ------------------- K2: crit -> q_crit -> u, cst ---------------------------
__global__ void k2_crit(const float* __restrict__ feats,
                        const float* __restrict__ w_q,
                        const float* __restrict__ b_q)
{
    const int b = blockIdx.x, tid = threadIdx.x;
    __shared__ float sx[NF], sq[DQ];
    __shared__ int s_crit;
    if (tid == 0)
        s_crit = N_TOT - (int)(unsigned)(g_argmax[b] & 0xffffffffull);
    __syncthreads();
    const float* x = feats + (size_t)s_crit * NF;
    for (int i = tid; i < NF; i += 128) sx[i] = x[i];
    __syncthreads();
    float q = b_q[tid];
    for (int f = 0; f < NF; f++) q += sx[f] * w_q[f * DQ + tid];
    sq[tid] = q;
    __syncthreads();
    for (int f = tid; f < NF; f += 128) {
        float uu = 0.f;
        for (int d = 0; d < DQ; d++) uu += w_q[f * DQ + d] * sq[d];
        g_u[b * NF + f] = uu;
    }
    if (tid == 0) {
        float cc = 0.f;
        for (int d = 0; d < DQ; d++) cc += b_q[d] * sq[d];
        g_cst[b] = cc;
    }
}

// ------------------- K3: A pass (exact fp32) + bag max ----------------------
__global__ void k3_attn(const float* __restrict__ feats) {
    __shared__ int s_offs[NBAGS + 1];
    __shared__ float s_cst[NBAGS];
    const int tid = threadIdx.x, wid = tid >> 5, lane = tid & 31;
    if (tid < NBAGS + 1) s_offs[tid] = g_offs[tid];
    if (tid < NBAGS) s_cst[tid] = g_cst[tid];
    __syncthreads();
    const int row = blockIdx.x * 8 + wid;
    const int bag = findbag(s_offs, row);
    const float* x = feats + (size_t)row * NF;
    const float* u = g_u + bag * NF;
    float s = 0.f;
    #pragma unroll
    for (int j = 0; j < 16; j++) {
        int f = lane + 32 * j;
        s = fmaf(x[f], u[f], s);
    }
    #pragma unroll
    for (int o = 16; o; o >>= 1) s += __shfl_xor_sync(0xffffffffu, s, o);
    if (lane == 0) {
        float A = (s + s_cst[bag]) * 0.08838834764831843f;  // 1/sqrt(128)
        g_A[row] = A;
        atomicMax(&g_bagAmax[bag], encf(A));
    }
}

// ------------------- K4: softmax weights + weighted sums --------------------
__global__ void k4_soft() {
    __shared__ int s_offs[NBAGS + 1];
    __shared__ float snum[NBAGS], sden[NBAGS];
    const int tid = threadIdx.x;
    if (tid < NBAGS + 1) s_offs[tid] = g_offs[tid];
    if (tid < NBAGS) { snum[tid] = 0.f; sden[tid] = 0.f; }
    __syncthreads();
    const int n = blockIdx.x * 256 + tid;
    const int bag = findbag(s_offs, n);
    const float m = decf(g_bagAmax[bag]);
    const float e = __expf(g_A[n] - m);
    atomicAdd(&snum[bag], e * g_vdot[n]);
    atomicAdd(&sden[bag], e);
    __syncthreads();
    if (tid < NBAGS && sden[tid] != 0.f) {
        atomicAdd(&g_num[tid], snum[tid]);
        atomicAdd(&g_den[tid], sden[tid]);
    }
}

// ------------------- K5: finalize bag_pred ----------------------------------
__global__ void k5_final(const float* __restrict__ fcc_b, float* __restrict__ out) {
    int b = threadIdx.x;
    if (b < NBAGS) out[b] = g_num[b] / g_den[b] + fcc_b[0];
}

// ----------------------------- launch ---------------------------------------
extern "C" void kernel_launch(void* const* d_in, const int* in_sizes, int n_in,
                              void* d_out, int out_size) {
    const float* feats  = (const float*)d_in[0];
    const int*   split  = (const int*)d_in[1];
    const float* w_ins  = (const float*)d_in[2];
    const float* b_ins  = (const float*)d_in[3];
    const float* w_q    = (const float*)d_in[4];
    const float* b_q    = (const float*)d_in[5];
    const float* w_v    = (const float*)d_in[6];
    const float* b_v    = (const float*)d_in[7];
    const float* fcc_w  = (const float*)d_in[8];
    const float* fcc_b  = (const float*)d_in[9];
    float* out = (float*)d_out;
    float* out_c = out + NBAGS;

    cudaFuncSetAttribute(k1_gemm, cudaFuncAttributeMaxDynamicSharedMemorySize,
                         SMEM_DYN);

    k0_init<<<1, 64>>>(split);
    kw_prep<<<NF * NF / 256, 256>>>(w_v);
    k1_gemm<<<N_TOT / BM, 256, SMEM_DYN>>>(feats, w_ins, b_ins, b_v, fcc_w, out_c);
    k2_crit<<<NBAGS, DQ>>>(feats, w_q, b_q);
    k3_attn<<<N_TOT / 8, 256>>>(feats);
    k4_soft<<<N_TOT / 256, 256>>>();
    k5_final<<<1, NBAGS>>>(fcc_b, out);
}